// round 9
// baseline (speedup 1.0000x reference)
#include <cuda_runtime.h>
#include <cstdint>
#include <cmath>

// ---------------------------------------------------------------------------
// L1Wav prox, fused-per-level: each level = ONE forward kernel (both axes +
// detail threshold) and ONE inverse kernel (both axes). 8 launches total.
// Storage: g_A = compact detail planes (3 per level, stride h_l);
//          g_B = LL chain (compact, stride h_l). Output is real-only float32
//          (established R7); roll fused into fwd-L0, un-roll into inv-L0.
// Phase cancels exactly; SHIFT replicated on host (numpy PCG64).
// ---------------------------------------------------------------------------

#define THRESH 0.005f

#define DECL_FILTERS \
    const float LO[8] = { \
        -0.010597401784997278f,  0.032883011666982945f,  0.030841381835986965f, \
        -0.18703481171888114f,  -0.02798376941698385f,   0.6308807679295904f, \
         0.7148465705525415f,    0.23037781330885523f }; \
    const float HI[8] = { \
         0.23037781330885523f,  -0.7148465705525415f,    0.6308807679295904f, \
         0.02798376941698385f,  -0.18703481171888114f,  -0.030841381835986965f, \
         0.032883011666982945f,  0.010597401784997278f };

// details: 3*(2048^2 + 1024^2 + 512^2 + 256^2) = 16,711,680 float2
__device__ float2 g_A[16711680u];
// LL chain: 2048^2 + 1024^2 + 512^2 + 256^2 = 5,570,560 float2
__device__ float2 g_B[5570560u];

__device__ __forceinline__ float2 softt(float2 v) {
    float m2 = v.x * v.x + v.y * v.y;
    if (m2 <= THRESH * THRESH) return make_float2(0.f, 0.f);
    float s = 1.0f - THRESH * rsqrtf(m2);
    return make_float2(v.x * s, v.y * s);
}

// Tile: TY=16, TX=32 (subband coords). Input region 40 x 72.

// ======================= FORWARD (generic, levels 1-3) ======================
__global__ __launch_bounds__(256)
void k_fwd(unsigned src_off, unsigned N, unsigned ll_off, unsigned det_off,
           int mode) {
    __shared__ float2 s1e[40][36];
    __shared__ float2 s1o[40][36];
    __shared__ float2 s2[40][64];
    DECL_FILTERS
    unsigned h = N >> 1;
    unsigned x0 = blockIdx.x * 32u;
    unsigned y0 = blockIdx.y * 16u;
    const float2* src = g_B + src_off;

    for (unsigned idx = threadIdx.x; idx < 40u * 72u; idx += 256u) {
        unsigned r = idx / 72u, c = idx % 72u;
        unsigned gr = (2u * y0 + r) & (N - 1u);
        unsigned gc = (2u * x0 + c) & (N - 1u);
        float2 v = src[gr * N + gc];
        if (c & 1u) s1o[r][c >> 1] = v; else s1e[r][c >> 1] = v;
    }
    __syncthreads();

    // axis1 transform: items (r, mm) -> a to s2[r][mm], d to s2[r][mm+32]
    for (unsigned idx = threadIdx.x; idx < 40u * 32u; idx += 256u) {
        unsigned r = idx >> 5, mm = idx & 31u;
        float2 a = {0, 0}, d = {0, 0};
#pragma unroll
        for (int t = 0; t < 4; t++) {
            float2 ve = s1e[r][mm + t];
            float2 vo = s1o[r][mm + t];
            a.x = fmaf(LO[2*t],   ve.x, a.x); a.y = fmaf(LO[2*t],   ve.y, a.y);
            a.x = fmaf(LO[2*t+1], vo.x, a.x); a.y = fmaf(LO[2*t+1], vo.y, a.y);
            d.x = fmaf(HI[2*t],   ve.x, d.x); d.y = fmaf(HI[2*t],   ve.y, d.y);
            d.x = fmaf(HI[2*t+1], vo.x, d.x); d.y = fmaf(HI[2*t+1], vo.y, d.y);
        }
        s2[r][mm] = a;
        s2[r][mm + 32] = d;
    }
    __syncthreads();

    // axis0 transform + dispatch
    float2* ll = g_B + ll_off;
    float2* lh = g_A + det_off;
    float2* hl = lh + h * h;
    float2* hh = hl + h * h;
    for (unsigned idx = threadIdx.x; idx < 16u * 64u; idx += 256u) {
        unsigned n = idx >> 6, m = idx & 63u;
        float2 A = {0, 0}, D = {0, 0};
#pragma unroll
        for (int k = 0; k < 8; k++) {
            float2 v = s2[2u * n + k][m];
            A.x = fmaf(LO[k], v.x, A.x); A.y = fmaf(LO[k], v.y, A.y);
            D.x = fmaf(HI[k], v.x, D.x); D.y = fmaf(HI[k], v.y, D.y);
        }
        unsigned gy = y0 + n;
        if (m < 32u) {
            unsigned gx = x0 + m;
            ll[gy * h + gx] = (mode == 2) ? softt(A) : A;
            hl[gy * h + gx] = softt(D);
        } else {
            unsigned gx = x0 + (m - 32u);
            lh[gy * h + gx] = softt(A);
            hh[gy * h + gx] = softt(D);
        }
    }
}

// ======================= FORWARD level 0 (input + roll) =====================
__global__ __launch_bounds__(256)
void k_fwd0(const float* __restrict__ xr, const float* __restrict__ xi,
            unsigned ll_off, unsigned det_off, int sh) {
    __shared__ float2 s1e[40][36];
    __shared__ float2 s1o[40][36];
    __shared__ float2 s2[40][64];
    DECL_FILTERS
    const unsigned N = 4096u, h = 2048u;
    unsigned x0 = blockIdx.x * 32u;
    unsigned y0 = blockIdx.y * 16u;

    for (unsigned idx = threadIdx.x; idx < 40u * 72u; idx += 256u) {
        unsigned r = idx / 72u, c = idx % 72u;
        unsigned gr = (2u * y0 + r - (unsigned)sh) & (N - 1u);
        unsigned gc = (2u * x0 + c - (unsigned)sh) & (N - 1u);
        float2 v = make_float2(xr[gr * N + gc], xi[gr * N + gc]);
        if (c & 1u) s1o[r][c >> 1] = v; else s1e[r][c >> 1] = v;
    }
    __syncthreads();

    for (unsigned idx = threadIdx.x; idx < 40u * 32u; idx += 256u) {
        unsigned r = idx >> 5, mm = idx & 31u;
        float2 a = {0, 0}, d = {0, 0};
#pragma unroll
        for (int t = 0; t < 4; t++) {
            float2 ve = s1e[r][mm + t];
            float2 vo = s1o[r][mm + t];
            a.x = fmaf(LO[2*t],   ve.x, a.x); a.y = fmaf(LO[2*t],   ve.y, a.y);
            a.x = fmaf(LO[2*t+1], vo.x, a.x); a.y = fmaf(LO[2*t+1], vo.y, a.y);
            d.x = fmaf(HI[2*t],   ve.x, d.x); d.y = fmaf(HI[2*t],   ve.y, d.y);
            d.x = fmaf(HI[2*t+1], vo.x, d.x); d.y = fmaf(HI[2*t+1], vo.y, d.y);
        }
        s2[r][mm] = a;
        s2[r][mm + 32] = d;
    }
    __syncthreads();

    float2* ll = g_B + ll_off;
    float2* lh = g_A + det_off;
    float2* hl = lh + h * h;
    float2* hh = hl + h * h;
    for (unsigned idx = threadIdx.x; idx < 16u * 64u; idx += 256u) {
        unsigned n = idx >> 6, m = idx & 63u;
        float2 A = {0, 0}, D = {0, 0};
#pragma unroll
        for (int k = 0; k < 8; k++) {
            float2 v = s2[2u * n + k][m];
            A.x = fmaf(LO[k], v.x, A.x); A.y = fmaf(LO[k], v.y, A.y);
            D.x = fmaf(HI[k], v.x, D.x); D.y = fmaf(HI[k], v.y, D.y);
        }
        unsigned gy = y0 + n;
        if (m < 32u) {
            unsigned gx = x0 + m;
            ll[gy * h + gx] = A;
            hl[gy * h + gx] = softt(D);
        } else {
            unsigned gx = x0 + (m - 32u);
            lh[gy * h + gx] = softt(A);
            hh[gy * h + gx] = softt(D);
        }
    }
}

// ======================= INVERSE (generic, levels 3-1) ======================
__global__ __launch_bounds__(256)
void k_inv(unsigned ll_off, unsigned det_off, unsigned h, unsigned dst_off) {
    __shared__ float2 sq[4][20][36];
    __shared__ float2 sAD[2][20][64];
    DECL_FILTERS
    unsigned x0 = blockIdx.x * 32u;
    unsigned y0 = blockIdx.y * 16u;
    const float2* ll = g_B + ll_off;
    const float2* lh = g_A + det_off;
    const float2* hl = lh + h * h;
    const float2* hh = hl + h * h;

    for (unsigned idx = threadIdx.x; idx < 4u * 20u * 36u; idx += 256u) {
        unsigned p = idx / 720u, rem = idx % 720u;
        unsigned t = rem / 36u, u = rem % 36u;
        unsigned gy = (y0 + t - 3u) & (h - 1u);
        unsigned gx = (x0 + u - 3u) & (h - 1u);
        const float2* pl = (p == 0) ? ll : (p == 1) ? lh : (p == 2) ? hl : hh;
        sq[p][t][u] = pl[gy * h + gx];
    }
    __syncthreads();

    // axis1 synthesis: (s,t,m) -> sAD[s][t][2m], [2m+1]
    for (unsigned idx = threadIdx.x; idx < 2u * 20u * 32u; idx += 256u) {
        unsigned s = idx / 640u, rem = idx % 640u;
        unsigned t = rem >> 5, m = rem & 31u;
        const float2 (*qa)[36] = sq[2 * s];       // LL or HL
        const float2 (*qd)[36] = sq[2 * s + 1];   // LH or HH
        float2 e = {0, 0}, o = {0, 0};
#pragma unroll
        for (int q = 0; q < 4; q++) {
            float2 a = qa[t][3 + m - q];
            float2 d = qd[t][3 + m - q];
            e.x = fmaf(LO[2*q],   a.x, e.x); e.y = fmaf(LO[2*q],   a.y, e.y);
            e.x = fmaf(HI[2*q],   d.x, e.x); e.y = fmaf(HI[2*q],   d.y, e.y);
            o.x = fmaf(LO[2*q+1], a.x, o.x); o.y = fmaf(LO[2*q+1], a.y, o.y);
            o.x = fmaf(HI[2*q+1], d.x, o.x); o.y = fmaf(HI[2*q+1], d.y, o.y);
        }
        sAD[s][t][2 * m] = e;
        sAD[s][t][2 * m + 1] = o;
    }
    __syncthreads();

    // axis0 synthesis -> dst (dim = 2h)
    float2* dst = g_B + dst_off;
    unsigned dim = 2u * h;
    for (unsigned idx = threadIdx.x; idx < 16u * 64u; idx += 256u) {
        unsigned n = idx >> 6, c = idx & 63u;
        float2 e = {0, 0}, o = {0, 0};
#pragma unroll
        for (int q = 0; q < 4; q++) {
            float2 a = sAD[0][3 + n - q][c];
            float2 d = sAD[1][3 + n - q][c];
            e.x = fmaf(LO[2*q],   a.x, e.x); e.y = fmaf(LO[2*q],   a.y, e.y);
            e.x = fmaf(HI[2*q],   d.x, e.x); e.y = fmaf(HI[2*q],   d.y, e.y);
            o.x = fmaf(LO[2*q+1], a.x, o.x); o.y = fmaf(LO[2*q+1], a.y, o.y);
            o.x = fmaf(HI[2*q+1], d.x, o.x); o.y = fmaf(HI[2*q+1], d.y, o.y);
        }
        unsigned gr = 2u * y0 + 2u * n;
        unsigned gc = 2u * x0 + c;
        dst[gr * dim + gc] = e;
        dst[(gr + 1u) * dim + gc] = o;
    }
}

// ============== INVERSE level 0: write real-only + un-roll ==================
__global__ __launch_bounds__(256)
void k_inv0_r(float* __restrict__ out, unsigned ll_off, unsigned det_off,
              int sh) {
    __shared__ float2 sq[4][20][36];
    __shared__ float2 sAD[2][20][64];
    DECL_FILTERS
    const unsigned h = 2048u;
    unsigned x0 = blockIdx.x * 32u;
    unsigned y0 = blockIdx.y * 16u;
    const float2* ll = g_B + ll_off;
    const float2* lh = g_A + det_off;
    const float2* hl = lh + h * h;
    const float2* hh = hl + h * h;

    for (unsigned idx = threadIdx.x; idx < 4u * 20u * 36u; idx += 256u) {
        unsigned p = idx / 720u, rem = idx % 720u;
        unsigned t = rem / 36u, u = rem % 36u;
        unsigned gy = (y0 + t - 3u) & (h - 1u);
        unsigned gx = (x0 + u - 3u) & (h - 1u);
        const float2* pl = (p == 0) ? ll : (p == 1) ? lh : (p == 2) ? hl : hh;
        sq[p][t][u] = pl[gy * h + gx];
    }
    __syncthreads();

    for (unsigned idx = threadIdx.x; idx < 2u * 20u * 32u; idx += 256u) {
        unsigned s = idx / 640u, rem = idx % 640u;
        unsigned t = rem >> 5, m = rem & 31u;
        const float2 (*qa)[36] = sq[2 * s];
        const float2 (*qd)[36] = sq[2 * s + 1];
        float2 e = {0, 0}, o = {0, 0};
#pragma unroll
        for (int q = 0; q < 4; q++) {
            float2 a = qa[t][3 + m - q];
            float2 d = qd[t][3 + m - q];
            e.x = fmaf(LO[2*q],   a.x, e.x); e.y = fmaf(LO[2*q],   a.y, e.y);
            e.x = fmaf(HI[2*q],   d.x, e.x); e.y = fmaf(HI[2*q],   d.y, e.y);
            o.x = fmaf(LO[2*q+1], a.x, o.x); o.y = fmaf(LO[2*q+1], a.y, o.y);
            o.x = fmaf(HI[2*q+1], d.x, o.x); o.y = fmaf(HI[2*q+1], d.y, o.y);
        }
        sAD[s][t][2 * m] = e;
        sAD[s][t][2 * m + 1] = o;
    }
    __syncthreads();

    for (unsigned idx = threadIdx.x; idx < 16u * 64u; idx += 256u) {
        unsigned n = idx >> 6, c = idx & 63u;
        float e = 0.f, o = 0.f;       // real parts only
#pragma unroll
        for (int q = 0; q < 4; q++) {
            float2 a = sAD[0][3 + n - q][c];
            float2 d = sAD[1][3 + n - q][c];
            e = fmaf(LO[2*q],   a.x, e);
            e = fmaf(HI[2*q],   d.x, e);
            o = fmaf(LO[2*q+1], a.x, o);
            o = fmaf(HI[2*q+1], d.x, o);
        }
        unsigned gr = 2u * y0 + 2u * n;
        unsigned gc = 2u * x0 + c;
        unsigned oc = (gc - (unsigned)sh) & 4095u;
        unsigned or0 = (gr - (unsigned)sh) & 4095u;
        unsigned or1 = (gr + 1u - (unsigned)sh) & 4095u;
        out[or0 * 4096u + oc] = e;
        out[or1 * 4096u + oc] = o;
    }
}

// ---- defensive complex-output variant (if out_size turns out >= 33.5M) ----
__global__ __launch_bounds__(256)
void k_inv0_c(float2* __restrict__ out, unsigned ll_off, unsigned det_off,
              int sh) {
    __shared__ float2 sq[4][20][36];
    __shared__ float2 sAD[2][20][64];
    DECL_FILTERS
    const unsigned h = 2048u;
    unsigned x0 = blockIdx.x * 32u;
    unsigned y0 = blockIdx.y * 16u;
    const float2* ll = g_B + ll_off;
    const float2* lh = g_A + det_off;
    const float2* hl = lh + h * h;
    const float2* hh = hl + h * h;
    for (unsigned idx = threadIdx.x; idx < 4u * 20u * 36u; idx += 256u) {
        unsigned p = idx / 720u, rem = idx % 720u;
        unsigned t = rem / 36u, u = rem % 36u;
        unsigned gy = (y0 + t - 3u) & (h - 1u);
        unsigned gx = (x0 + u - 3u) & (h - 1u);
        const float2* pl = (p == 0) ? ll : (p == 1) ? lh : (p == 2) ? hl : hh;
        sq[p][t][u] = pl[gy * h + gx];
    }
    __syncthreads();
    for (unsigned idx = threadIdx.x; idx < 2u * 20u * 32u; idx += 256u) {
        unsigned s = idx / 640u, rem = idx % 640u;
        unsigned t = rem >> 5, m = rem & 31u;
        const float2 (*qa)[36] = sq[2 * s];
        const float2 (*qd)[36] = sq[2 * s + 1];
        float2 e = {0, 0}, o = {0, 0};
#pragma unroll
        for (int q = 0; q < 4; q++) {
            float2 a = qa[t][3 + m - q];
            float2 d = qd[t][3 + m - q];
            e.x = fmaf(LO[2*q],   a.x, e.x); e.y = fmaf(LO[2*q],   a.y, e.y);
            e.x = fmaf(HI[2*q],   d.x, e.x); e.y = fmaf(HI[2*q],   d.y, e.y);
            o.x = fmaf(LO[2*q+1], a.x, o.x); o.y = fmaf(LO[2*q+1], a.y, o.y);
            o.x = fmaf(HI[2*q+1], d.x, o.x); o.y = fmaf(HI[2*q+1], d.y, o.y);
        }
        sAD[s][t][2 * m] = e;
        sAD[s][t][2 * m + 1] = o;
    }
    __syncthreads();
    for (unsigned idx = threadIdx.x; idx < 16u * 64u; idx += 256u) {
        unsigned n = idx >> 6, c = idx & 63u;
        float2 e = {0, 0}, o = {0, 0};
#pragma unroll
        for (int q = 0; q < 4; q++) {
            float2 a = sAD[0][3 + n - q][c];
            float2 d = sAD[1][3 + n - q][c];
            e.x = fmaf(LO[2*q],   a.x, e.x); e.y = fmaf(LO[2*q],   a.y, e.y);
            e.x = fmaf(HI[2*q],   d.x, e.x); e.y = fmaf(HI[2*q],   d.y, e.y);
            o.x = fmaf(LO[2*q+1], a.x, o.x); o.y = fmaf(LO[2*q+1], a.y, o.y);
            o.x = fmaf(HI[2*q+1], d.x, o.x); o.y = fmaf(HI[2*q+1], d.y, o.y);
        }
        unsigned gr = 2u * y0 + 2u * n;
        unsigned gc = 2u * x0 + c;
        unsigned oc = (gc - (unsigned)sh) & 4095u;
        unsigned or0 = (gr - (unsigned)sh) & 4095u;
        unsigned or1 = (gr + 1u - (unsigned)sh) & 4095u;
        out[or0 * 4096u + oc] = e;
        out[or1 * 4096u + oc] = o;
    }
}

// ---------------------------------------------------------------------------
// Host: replicate numpy default_rng(1000).uniform(-3,3) -> SHIFT
// ---------------------------------------------------------------------------
static int compute_shift() {
    const uint32_t MULT_A = 0x931e8875u, INIT_A = 0x43b0d7e5u;
    const uint32_t MULT_B = 0x58f38dedu, INIT_B = 0x8b51f9ddu;
    const uint32_t MIX_L = 0xca01f9ddu, MIX_R = 0x4973f715u;

    uint32_t hc = INIT_A;
    auto hashmix = [&](uint32_t v) -> uint32_t {
        v ^= hc; hc *= MULT_A; v *= hc; v ^= v >> 16; return v;
    };
    auto mix = [&](uint32_t x, uint32_t y) -> uint32_t {
        uint32_t r = (x * MIX_L) ^ (y * MIX_R); r ^= r >> 16; return r;
    };

    uint32_t pool[4];
    for (int i = 0; i < 4; i++) pool[i] = hashmix(i < 1 ? 1000u : 0u);
    for (int s = 0; s < 4; s++)
        for (int d = 0; d < 4; d++)
            if (s != d) pool[d] = mix(pool[d], hashmix(pool[s]));

    uint32_t st[8];
    uint32_t hb = INIT_B;
    for (int i = 0; i < 8; i++) {
        uint32_t v = pool[i & 3];
        v ^= hb; hb *= MULT_B; v *= hb; v ^= v >> 16;
        st[i] = v;
    }
    uint64_t w[4];
    for (int i = 0; i < 4; i++)
        w[i] = (uint64_t)st[2 * i] | ((uint64_t)st[2 * i + 1] << 32);

    typedef unsigned __int128 u128;
    const u128 MULT = ((u128)2549297995355413924ULL << 64) | 4865540595714422341ULL;
    u128 initstate = ((u128)w[0] << 64) | w[1];
    u128 initseq   = ((u128)w[2] << 64) | w[3];
    u128 state = 0;
    u128 inc = (initseq << 1) | 1;
    state = state * MULT + inc;
    state += initstate;
    state = state * MULT + inc;
    state = state * MULT + inc;      // first next_uint64
    uint64_t xo = (uint64_t)(state >> 64) ^ (uint64_t)state;
    unsigned rot = (unsigned)(state >> 122);
    uint64_t out64 = (xo >> rot) | (xo << ((64u - rot) & 63u));
    double dd = (double)(out64 >> 11) * (1.0 / 9007199254740992.0);
    double u = -3.0 + 6.0 * dd;
    return (int)nearbyint(u);
}

extern "C" void kernel_launch(void* const* d_in, const int* in_sizes, int n_in,
                              void* d_out, int out_size) {
    const float* xr = (const float*)d_in[0];
    const float* xi = (n_in >= 2) ? (const float*)d_in[1] : (const float*)d_in[0];
    const int sh = compute_shift();

    // LL-chain offsets in g_B, detail-plane offsets in g_A
    const unsigned so0 = 0u;
    const unsigned so1 = so0 + 2048u * 2048u;
    const unsigned so2 = so1 + 1024u * 1024u;
    const unsigned so3 = so2 + 512u * 512u;
    const unsigned da0 = 0u;
    const unsigned da1 = da0 + 3u * 2048u * 2048u;
    const unsigned da2 = da1 + 3u * 1024u * 1024u;
    const unsigned da3 = da2 + 3u * 512u * 512u;

    dim3 blk(256);

    // ---- forward (fused per level) ----
    k_fwd0<<<dim3(64, 128), blk>>>(xr, xi, so0, da0, sh);
    k_fwd <<<dim3(32, 64),  blk>>>(so0, 2048u, so1, da1, 1);
    k_fwd <<<dim3(16, 32),  blk>>>(so1, 1024u, so2, da2, 1);
    k_fwd <<<dim3(8, 16),   blk>>>(so2,  512u, so3, da3, 2);  // + LL threshold

    // ---- inverse (fused per level) ----
    k_inv<<<dim3(8, 16),   blk>>>(so3, da3, 256u,  so2);
    k_inv<<<dim3(16, 32),  blk>>>(so2, da2, 512u,  so1);
    k_inv<<<dim3(32, 64),  blk>>>(so1, da1, 1024u, so0);

    if (out_size >= 2 * 16777216) {
        k_inv0_c<<<dim3(64, 128), blk>>>((float2*)d_out, so0, da0, sh);
    } else {
        k_inv0_r<<<dim3(64, 128), blk>>>((float*)d_out, so0, da0, sh);
    }
}

// round 10
// speedup vs baseline: 1.2669x; 1.2669x over previous
#include <cuda_runtime.h>
#include <cstdint>
#include <cmath>

// ---------------------------------------------------------------------------
// L1Wav prox (R10): R7 structure (separable passes, Mallat canvas in g_A,
// ping-pong g_B, both 4096-stride) with ONE change: vertical kernels chunk
// 8 consecutive n per block using a register sliding window (3-4x less
// L1/L2 read traffic). soft_ll folded into final-level fwd1 (mode=2).
// Output real-only float32 (established R7); roll fused fwd, un-roll inv.
// ---------------------------------------------------------------------------

#define STR 4096u
#define NTOP 4096u
#define THRESH 0.005f

#define DECL_FILTERS \
    const float LO[8] = { \
        -0.010597401784997278f,  0.032883011666982945f,  0.030841381835986965f, \
        -0.18703481171888114f,  -0.02798376941698385f,   0.6308807679295904f, \
         0.7148465705525415f,    0.23037781330885523f }; \
    const float HI[8] = { \
         0.23037781330885523f,  -0.7148465705525415f,    0.6308807679295904f, \
         0.02798376941698385f,  -0.18703481171888114f,  -0.030841381835986965f, \
         0.032883011666982945f,  0.010597401784997278f };

__device__ float2 g_A[STR * STR];
__device__ float2 g_B[STR * STR];

__device__ __forceinline__ void fma2(float2& a, float c, float2 v) {
    a.x = fmaf(c, v.x, a.x);
    a.y = fmaf(c, v.y, a.y);
}

__device__ __forceinline__ float2 softt(float2 v) {
    float m2 = v.x * v.x + v.y * v.y;
    if (m2 <= THRESH * THRESH) return make_float2(0.f, 0.f);
    float s = 1.0f - THRESH * rsqrtf(m2);
    return make_float2(v.x * s, v.y * s);
}

// ---- forward axis0 level 0, fused roll, CHUNK=8 n per block ----
__global__ __launch_bounds__(256)
void k_fwd0_roll(const float* __restrict__ xr, const float* __restrict__ xi,
                 int sh) {
    DECL_FILTERS
    unsigned j = blockIdx.x * 256u + threadIdx.x;    // 0..4095
    unsigned n0 = blockIdx.y * 8u;                   // chunk base
    unsigned jc = (j - (unsigned)sh) & (NTOP - 1u);
    float2 w[8];
#pragma unroll
    for (unsigned k = 0; k < 8u; k++) {
        unsigned r = (2u * n0 + k - (unsigned)sh) & (NTOP - 1u);
        w[k] = make_float2(xr[r * STR + jc], xi[r * STR + jc]);
    }
#pragma unroll
    for (unsigned m = 0; m < 8u; m++) {
        unsigned n = n0 + m;
        float2 a = {0, 0}, d = {0, 0};
#pragma unroll
        for (int k = 0; k < 8; k++) {
            fma2(a, LO[k], w[k]);
            fma2(d, HI[k], w[k]);
        }
        g_B[n * STR + j] = a;
        g_B[(n + (NTOP >> 1)) * STR + j] = d;
        if (m < 7u) {
#pragma unroll
            for (int k = 0; k < 6; k++) w[k] = w[k + 2];
            unsigned r0 = (2u * n + 8u - (unsigned)sh) & (NTOP - 1u);
            unsigned r1 = (2u * n + 9u - (unsigned)sh) & (NTOP - 1u);
            w[6] = make_float2(xr[r0 * STR + jc], xi[r0 * STR + jc]);
            w[7] = make_float2(xr[r1 * STR + jc], xi[r1 * STR + jc]);
        }
    }
}

// ---- forward axis0 generic: A -> B, chunked ----
__global__ __launch_bounds__(256)
void k_fwd0(unsigned N, unsigned chunk) {
    DECL_FILTERS
    unsigned j = blockIdx.x * 256u + threadIdx.x;
    if (j >= N) return;
    unsigned n0 = blockIdx.y * chunk;
    unsigned h = N >> 1;
    float2 w[8];
#pragma unroll
    for (unsigned k = 0; k < 8u; k++)
        w[k] = g_A[((2u * n0 + k) & (N - 1u)) * STR + j];
    for (unsigned m = 0; m < chunk; m++) {
        unsigned n = n0 + m;
        float2 a = {0, 0}, d = {0, 0};
#pragma unroll
        for (int k = 0; k < 8; k++) {
            fma2(a, LO[k], w[k]);
            fma2(d, HI[k], w[k]);
        }
        g_B[n * STR + j] = a;
        g_B[(n + h) * STR + j] = d;
        if (m + 1u < chunk) {
#pragma unroll
            for (int k = 0; k < 6; k++) w[k] = w[k + 2];
            w[6] = g_A[((2u * n + 8u) & (N - 1u)) * STR + j];
            w[7] = g_A[((2u * n + 9u) & (N - 1u)) * STR + j];
        }
    }
}

// ---- forward axis1 + threshold: B -> A (R7 body + mode) ----
// mode=1: details only (a when i>=h, d always). mode=2: all (LL too).
__global__ __launch_bounds__(256)
void k_fwd1(unsigned N, int mode) {
    DECL_FILTERS
    unsigned n = blockIdx.x * 256u + threadIdx.x;
    unsigned i = blockIdx.y;
    unsigned h = N >> 1;
    if (n >= h) return;
    float2 a = {0, 0}, d = {0, 0};
#pragma unroll
    for (unsigned k = 0; k < 8u; k++) {
        unsigned c = (2u * n + k) & (N - 1u);
        float2 v = g_B[i * STR + c];
        fma2(a, LO[k], v);
        fma2(d, HI[k], v);
    }
    bool ta = (mode == 2) || (i >= h);
    g_A[i * STR + n] = ta ? softt(a) : a;
    g_A[i * STR + h + n] = softt(d);
}

// ---- inverse axis1: A quadrants -> stacked a/d in B (R7 body) ----
__global__ __launch_bounds__(256)
void k_inv1(unsigned N) {
    DECL_FILTERS
    unsigned p = blockIdx.x * 256u + threadIdx.x;
    unsigned i = blockIdx.y;
    unsigned h = N >> 1;
    if (p >= h) return;
    float2 e = {0, 0}, o = {0, 0};
#pragma unroll
    for (unsigned q = 0; q < 4u; q++) {
        unsigned pp = (p - q + h) & (h - 1u);
        float2 s = g_A[i * STR + pp];
        float2 t = g_A[i * STR + h + pp];
        fma2(e, LO[2 * q], s);     fma2(e, HI[2 * q], t);
        fma2(o, LO[2 * q + 1], s); fma2(o, HI[2 * q + 1], t);
    }
    g_B[i * STR + 2u * p]      = e;
    g_B[i * STR + 2u * p + 1u] = o;
}

// ---- inverse axis0: B stacked -> A region, chunked sliding window ----
__global__ __launch_bounds__(256)
void k_inv0(unsigned N, unsigned chunk) {
    DECL_FILTERS
    unsigned j = blockIdx.x * 256u + threadIdx.x;
    if (j >= N) return;
    unsigned p0 = blockIdx.y * chunk;
    unsigned h = N >> 1;
    float2 wa[4], wd[4];                     // wa[i] = a[p-3+i]
#pragma unroll
    for (unsigned i = 0; i < 4u; i++) {
        unsigned pp = (p0 + i - 3u + h) & (h - 1u);
        wa[i] = g_B[pp * STR + j];
        wd[i] = g_B[(h + pp) * STR + j];
    }
    for (unsigned m = 0; m < chunk; m++) {
        unsigned p = p0 + m;
        float2 e = {0, 0}, o = {0, 0};
#pragma unroll
        for (int q = 0; q < 4; q++) {
            float2 s = wa[3 - q], t = wd[3 - q];
            fma2(e, LO[2 * q], s);     fma2(e, HI[2 * q], t);
            fma2(o, LO[2 * q + 1], s); fma2(o, HI[2 * q + 1], t);
        }
        g_A[(2u * p) * STR + j]      = e;
        g_A[(2u * p + 1u) * STR + j] = o;
        if (m + 1u < chunk) {
#pragma unroll
            for (int i = 0; i < 3; i++) { wa[i] = wa[i + 1]; wd[i] = wd[i + 1]; }
            unsigned pp = (p + 1u) & (h - 1u);
            wa[3] = g_B[pp * STR + j];
            wd[3] = g_B[(h + pp) * STR + j];
        }
    }
}

// ---- final inverse axis0 + un-roll, REAL-only output, chunked ----
__global__ __launch_bounds__(256)
void k_inv0_out_r(float* __restrict__ out, int sh) {
    DECL_FILTERS
    unsigned j = blockIdx.x * 256u + threadIdx.x;
    unsigned p0 = blockIdx.y * 8u;
    const unsigned h = NTOP >> 1;
    unsigned jc = (j - (unsigned)sh) & (NTOP - 1u);
    float2 wa[4], wd[4];
#pragma unroll
    for (unsigned i = 0; i < 4u; i++) {
        unsigned pp = (p0 + i - 3u + h) & (h - 1u);
        wa[i] = g_B[pp * STR + j];
        wd[i] = g_B[(h + pp) * STR + j];
    }
#pragma unroll
    for (unsigned m = 0; m < 8u; m++) {
        unsigned p = p0 + m;
        float e = 0.f, o = 0.f;              // real parts only
#pragma unroll
        for (int q = 0; q < 4; q++) {
            float sx = wa[3 - q].x, tx = wd[3 - q].x;
            e = fmaf(LO[2 * q], sx, e);     e = fmaf(HI[2 * q], tx, e);
            o = fmaf(LO[2 * q + 1], sx, o); o = fmaf(HI[2 * q + 1], tx, o);
        }
        unsigned r0 = (2u * p - (unsigned)sh) & (NTOP - 1u);
        unsigned r1 = (2u * p + 1u - (unsigned)sh) & (NTOP - 1u);
        out[r0 * NTOP + jc] = e;
        out[r1 * NTOP + jc] = o;
        if (m < 7u) {
#pragma unroll
            for (int i = 0; i < 3; i++) { wa[i] = wa[i + 1]; wd[i] = wd[i + 1]; }
            unsigned pp = (p + 1u) & (h - 1u);
            wa[3] = g_B[pp * STR + j];
            wd[3] = g_B[(h + pp) * STR + j];
        }
    }
}

// ---- defensive complex-output variant ----
__global__ __launch_bounds__(256)
void k_inv0_out_c(float2* __restrict__ out, int sh) {
    DECL_FILTERS
    unsigned j = blockIdx.x * 256u + threadIdx.x;
    unsigned p0 = blockIdx.y * 8u;
    const unsigned h = NTOP >> 1;
    unsigned jc = (j - (unsigned)sh) & (NTOP - 1u);
    float2 wa[4], wd[4];
#pragma unroll
    for (unsigned i = 0; i < 4u; i++) {
        unsigned pp = (p0 + i - 3u + h) & (h - 1u);
        wa[i] = g_B[pp * STR + j];
        wd[i] = g_B[(h + pp) * STR + j];
    }
#pragma unroll
    for (unsigned m = 0; m < 8u; m++) {
        unsigned p = p0 + m;
        float2 e = {0, 0}, o = {0, 0};
#pragma unroll
        for (int q = 0; q < 4; q++) {
            float2 s = wa[3 - q], t = wd[3 - q];
            fma2(e, LO[2 * q], s);     fma2(e, HI[2 * q], t);
            fma2(o, LO[2 * q + 1], s); fma2(o, HI[2 * q + 1], t);
        }
        unsigned r0 = (2u * p - (unsigned)sh) & (NTOP - 1u);
        unsigned r1 = (2u * p + 1u - (unsigned)sh) & (NTOP - 1u);
        out[r0 * NTOP + jc] = e;
        out[r1 * NTOP + jc] = o;
        if (m < 7u) {
#pragma unroll
            for (int i = 0; i < 3; i++) { wa[i] = wa[i + 1]; wd[i] = wd[i + 1]; }
            unsigned pp = (p + 1u) & (h - 1u);
            wa[3] = g_B[pp * STR + j];
            wd[3] = g_B[(h + pp) * STR + j];
        }
    }
}

// ---------------------------------------------------------------------------
// Host: replicate numpy default_rng(1000).uniform(-3,3) -> SHIFT
// ---------------------------------------------------------------------------
static int compute_shift() {
    const uint32_t MULT_A = 0x931e8875u, INIT_A = 0x43b0d7e5u;
    const uint32_t MULT_B = 0x58f38dedu, INIT_B = 0x8b51f9ddu;
    const uint32_t MIX_L = 0xca01f9ddu, MIX_R = 0x4973f715u;

    uint32_t hc = INIT_A;
    auto hashmix = [&](uint32_t v) -> uint32_t {
        v ^= hc; hc *= MULT_A; v *= hc; v ^= v >> 16; return v;
    };
    auto mix = [&](uint32_t x, uint32_t y) -> uint32_t {
        uint32_t r = (x * MIX_L) ^ (y * MIX_R); r ^= r >> 16; return r;
    };

    uint32_t pool[4];
    for (int i = 0; i < 4; i++) pool[i] = hashmix(i < 1 ? 1000u : 0u);
    for (int s = 0; s < 4; s++)
        for (int d = 0; d < 4; d++)
            if (s != d) pool[d] = mix(pool[d], hashmix(pool[s]));

    uint32_t st[8];
    uint32_t hb = INIT_B;
    for (int i = 0; i < 8; i++) {
        uint32_t v = pool[i & 3];
        v ^= hb; hb *= MULT_B; v *= hb; v ^= v >> 16;
        st[i] = v;
    }
    uint64_t w[4];
    for (int i = 0; i < 4; i++)
        w[i] = (uint64_t)st[2 * i] | ((uint64_t)st[2 * i + 1] << 32);

    typedef unsigned __int128 u128;
    const u128 MULT = ((u128)2549297995355413924ULL << 64) | 4865540595714422341ULL;
    u128 initstate = ((u128)w[0] << 64) | w[1];
    u128 initseq   = ((u128)w[2] << 64) | w[3];
    u128 state = 0;
    u128 inc = (initseq << 1) | 1;
    state = state * MULT + inc;
    state += initstate;
    state = state * MULT + inc;
    state = state * MULT + inc;      // first next_uint64
    uint64_t xo = (uint64_t)(state >> 64) ^ (uint64_t)state;
    unsigned rot = (unsigned)(state >> 122);
    uint64_t out64 = (xo >> rot) | (xo << ((64u - rot) & 63u));
    double dd = (double)(out64 >> 11) * (1.0 / 9007199254740992.0);
    double u = -3.0 + 6.0 * dd;
    return (int)nearbyint(u);
}

extern "C" void kernel_launch(void* const* d_in, const int* in_sizes, int n_in,
                              void* d_out, int out_size) {
    const float* xr = (const float*)d_in[0];
    const float* xi = (n_in >= 2) ? (const float*)d_in[1] : (const float*)d_in[0];
    const int sh = compute_shift();

    dim3 blk(256);

    // ---- forward ----
    k_fwd0_roll<<<dim3(16, 256), blk>>>(xr, xi, sh);           // 2048/8 chunks
    k_fwd1<<<dim3(8, 4096), blk>>>(4096u, 1);
    // N=2048
    k_fwd0<<<dim3(8, 128), blk>>>(2048u, 8u);
    k_fwd1<<<dim3(4, 2048), blk>>>(2048u, 1);
    // N=1024
    k_fwd0<<<dim3(4, 64), blk>>>(1024u, 8u);
    k_fwd1<<<dim3(2, 1024), blk>>>(1024u, 1);
    // N=512 (chunk=1; fold LL threshold into fwd1 via mode=2)
    k_fwd0<<<dim3(2, 256), blk>>>(512u, 1u);
    k_fwd1<<<dim3(1, 512), blk>>>(512u, 2);

    // ---- inverse ----
    k_inv1<<<dim3(1, 512), blk>>>(512u);
    k_inv0<<<dim3(2, 256), blk>>>(512u, 1u);
    k_inv1<<<dim3(2, 1024), blk>>>(1024u);
    k_inv0<<<dim3(4, 64), blk>>>(1024u, 8u);
    k_inv1<<<dim3(4, 2048), blk>>>(2048u);
    k_inv0<<<dim3(8, 128), blk>>>(2048u, 8u);
    k_inv1<<<dim3(8, 4096), blk>>>(4096u);

    if (out_size >= 2 * 16777216) {
        k_inv0_out_c<<<dim3(16, 256), blk>>>((float2*)d_out, sh);
    } else {
        k_inv0_out_r<<<dim3(16, 256), blk>>>((float*)d_out, sh);
    }
}